// round 4
// baseline (speedup 1.0000x reference)
#include <cuda_runtime.h>
#include <cuda_bf16.h>
#include <cstdint>
#include <math.h>

#define NROWS 8192
#define HSZ (NROWS * 32)
#define NSPLIT 4
#define JSPLIT (NROWS / NSPLIT)        // 2048 j per CTA
#define CHUNKJ 64
#define NCHUNK (JSPLIT / CHUNKJ)       // 32 chunks
#define PITCH80 80                     // smem pitch: 64B data + 16 pad (5 mod 8 -> conflict-free ldmatrix)
#define MSTR (64 * PITCH80)            // 5120 per mask
#define BUFB (3 * MSTR)                // 15360 per buffer
#define SMEM_DYN (2 * BUFB)            // 30720

// ---------------- device scratch ----------------
__device__ float g_Z[HSZ];
__device__ float g_PartZ[NSPLIT * HSZ];
__device__ float g_colsum[32 * 32];
__device__ float g_HT[3 * 32 * NROWS];               // H^T fp32 [k*32+c][j]
__device__ signed char g_GQ[3 * 64 * NROWS];          // s8 [k*64 + (c | hi/lo)][j]
__device__ int g_cmaxi[2][32];                        // per-layer per-channel max|H| (float bits)
__device__ unsigned char g_adjB[(size_t)NROWS * NROWS]; // byte-packed adj (layer-1 side channel)

// ---------------- helpers ----------------
__device__ __forceinline__ uint32_t smem_u32(const void* p) {
    uint32_t a;
    asm("{ .reg .u64 t; cvta.to.shared.u64 t, %1; cvt.u32.u64 %0, t; }" : "=r"(a) : "l"(p));
    return a;
}
__device__ __forceinline__ void cp16(uint32_t dst, const void* src) {
    asm volatile("cp.async.cg.shared.global [%0], [%1], 16;" :: "r"(dst), "l"(src) : "memory");
}
__device__ __forceinline__ void cp_commit() { asm volatile("cp.async.commit_group;" ::: "memory"); }
__device__ __forceinline__ void cp_wait1()  { asm volatile("cp.async.wait_group 1;" ::: "memory"); }
__device__ __forceinline__ void cp_wait0()  { asm volatile("cp.async.wait_group 0;" ::: "memory"); }

__device__ __forceinline__ void ldm4(uint32_t* r, uint32_t addr) {
    asm volatile("ldmatrix.sync.aligned.m8n8.x4.shared.b16 {%0,%1,%2,%3}, [%4];"
                 : "=r"(r[0]), "=r"(r[1]), "=r"(r[2]), "=r"(r[3]) : "r"(addr));
}
__device__ __forceinline__ void mma_s8(int* c, const uint32_t* a, uint32_t b0, uint32_t b1) {
    asm volatile(
        "mma.sync.aligned.m16n8k32.row.col.s32.s8.s8.s32 "
        "{%0,%1,%2,%3}, {%4,%5,%6,%7}, {%8,%9}, {%0,%1,%2,%3};"
        : "+r"(c[0]), "+r"(c[1]), "+r"(c[2]), "+r"(c[3])
        : "r"(a[0]), "r"(a[1]), "r"(a[2]), "r"(a[3]), "r"(b0), "r"(b1));
}
__device__ __forceinline__ uint32_t pack4(int4 v) {
    uint32_t p1 = __byte_perm((uint32_t)v.x, (uint32_t)v.y, 0x0040);
    uint32_t p2 = __byte_perm((uint32_t)v.z, (uint32_t)v.w, 0x0040);
    return __byte_perm(p1, p2, 0x5410);       // [x0,y0,z0,w0]
}

// ---------------- init: zero colsum + both scale buffers ----------------
__global__ void init_kernel() {
    int idx = blockIdx.x * blockDim.x + threadIdx.x;
    if (idx < 1024) g_colsum[idx] = 0.0f;
    if (idx < 64) ((int*)g_cmaxi)[idx] = 0;
}

// ---------------- H^T = (V or Z) @ w_k, fp32 + per-channel max ----------------
__global__ void gt_kernel(const float* __restrict__ Vin, int useZ,
                          const float* __restrict__ w1,
                          const float* __restrict__ w2,
                          const float* __restrict__ w3, int layer) {
    const float* Z = useZ ? g_Z : Vin;
    int tid = threadIdx.x, lane = tid & 31, w = tid >> 5;
    int j = blockIdx.x * 32 + lane;

    float z[32];
    #pragma unroll
    for (int q = 0; q < 8; q++) {
        float4 v = *(const float4*)(Z + (size_t)j * 32 + q * 4);
        z[q * 4 + 0] = v.x; z[q * 4 + 1] = v.y; z[q * 4 + 2] = v.z; z[q * 4 + 3] = v.w;
    }
    #pragma unroll
    for (int m = 0; m < 12; m++) {
        int row = w * 12 + m;                // 0..95
        int k = row >> 5, c = row & 31;
        const float* wk = (k == 0) ? w1 : ((k == 1) ? w2 : w3);
        float h = 0.f;
        #pragma unroll
        for (int i = 0; i < 32; i++) h = fmaf(z[i], __ldg(wk + i * 32 + c), h);
        g_HT[(size_t)row * NROWS + j] = h;
        float a = fabsf(h);
        #pragma unroll
        for (int o = 16; o; o >>= 1) a = fmaxf(a, __shfl_xor_sync(0xffffffffu, a, o));
        if (lane == 0) atomicMax(&g_cmaxi[layer][c], __float_as_int(a));
    }
}

// ---------------- quantize H -> s8 hi/lo ----------------
__global__ void quant_kernel(int layer) {
    int idx = blockIdx.x * 256 + threadIdx.x;     // 96 rows x 2048 j4
    int row = idx >> 11;
    int j4  = (idx & 2047) * 4;
    int k = row >> 5, c = row & 31;
    float M = fmaxf(__int_as_float(g_cmaxi[layer][c]), 1e-20f);
    float s_hi = 127.0f / M, inv_hi = M / 127.0f, s_lo = 16129.0f / M;
    float4 h = *(const float4*)(g_HT + (size_t)row * NROWS + j4);
    float hv[4] = {h.x, h.y, h.z, h.w};
    int qh[4], ql[4];
    #pragma unroll
    for (int e = 0; e < 4; e++) {
        int q1 = __float2int_rn(hv[e] * s_hi);
        q1 = max(-127, min(127, q1));
        float r = hv[e] - (float)q1 * inv_hi;
        int q2 = __float2int_rn(r * s_lo);
        q2 = max(-127, min(127, q2));
        qh[e] = q1; ql[e] = q2;
    }
    uchar4 vh, vl;
    vh.x = (unsigned char)(signed char)qh[0]; vh.y = (unsigned char)(signed char)qh[1];
    vh.z = (unsigned char)(signed char)qh[2]; vh.w = (unsigned char)(signed char)qh[3];
    vl.x = (unsigned char)(signed char)ql[0]; vl.y = (unsigned char)(signed char)ql[1];
    vl.z = (unsigned char)(signed char)ql[2]; vl.w = (unsigned char)(signed char)ql[3];
    *(uchar4*)(g_GQ + (size_t)(k * 64 + c) * NROWS + j4)      = vh;
    *(uchar4*)(g_GQ + (size_t)(k * 64 + 32 + c) * NROWS + j4) = vl;
}

// ---------------- masked aggregation: D^T = sum_k GQ_k^T @ M_k^T via mma.sync s8 ----------------
template<int L1>
__global__ void __launch_bounds__(256, 2) agg_kernel(const int* __restrict__ adj32) {
    extern __shared__ __align__(128) unsigned char dyn[];
    const uint32_t sb = smem_u32(dyn);

    const int tid = threadIdx.x, lane = tid & 31;
    const int w = tid >> 5, mh = w & 1, ih = w >> 1;    // mh: 0=hi rows, 1=lo rows
    const int g = lane >> 2, t = lane & 3;
    const int i0 = blockIdx.x * 128;
    const int j0 = blockIdx.y * JSPLIT;

    int acc[4][2][4];
    #pragma unroll
    for (int a = 0; a < 4; a++)
        #pragma unroll
        for (int b = 0; b < 2; b++)
            #pragma unroll
            for (int q = 0; q < 4; q++) acc[a][b][q] = 0;

    // ldmatrix per-lane offset within a (m, mt, ks) tile
    const uint32_t lmo = (uint32_t)(((lane & 7) + ((lane >> 3) & 1) * 8) * PITCH80
                                    + (lane >> 4) * 16);

    // stage chunk 0 (GQ -> smem, 192 rows x 64B)
    {
        #pragma unroll
        for (int q = 0; q < 3; q++) {
            int idx = tid + 256 * q;
            int row = idx >> 2, seg = idx & 3;
            cp16(sb + (row >> 6) * MSTR + (row & 63) * PITCH80 + seg * 16,
                 g_GQ + (size_t)row * NROWS + j0 + seg * 16);
        }
        cp_commit();
    }

    for (int ch = 0; ch < NCHUNK; ch++) {
        const int jb = j0 + ch * CHUNKJ;
        uint32_t pk1[2][4], pk2[2][4];   // [ks][nt]

        if (L1) {
            #pragma unroll
            for (int nt = 0; nt < 4; nt++) {
                const int* ap = adj32 + (size_t)(i0 + ih * 32 + nt * 8 + g) * NROWS + jb;
                int4 a0 = *(const int4*)(ap +      4 * t);
                int4 b0 = *(const int4*)(ap + 16 + 4 * t);
                int4 a1 = *(const int4*)(ap + 32 + 4 * t);
                int4 b1 = *(const int4*)(ap + 48 + 4 * t);
                pk1[0][nt] = pack4(a0); pk2[0][nt] = pack4(b0);
                pk1[1][nt] = pack4(a1); pk2[1][nt] = pack4(b1);
                if (mh == 0) {
                    uint4 st = make_uint4(pk1[0][nt], pk2[0][nt], pk1[1][nt], pk2[1][nt]);
                    *(uint4*)(g_adjB + (size_t)(i0 + ih * 32 + nt * 8 + g) * NROWS + jb + 16 * t) = st;
                }
            }
        } else {
            #pragma unroll
            for (int nt = 0; nt < 4; nt++) {
                uint4 v = *(const uint4*)(g_adjB + (size_t)(i0 + ih * 32 + nt * 8 + g) * NROWS
                                          + jb + 16 * t);
                pk1[0][nt] = v.x; pk2[0][nt] = v.y; pk1[1][nt] = v.z; pk2[1][nt] = v.w;
            }
        }

        if (ch + 1 < NCHUNK) {
            const int jc = j0 + (ch + 1) * CHUNKJ;
            const uint32_t db = sb + ((ch + 1) & 1) * BUFB;
            #pragma unroll
            for (int q = 0; q < 3; q++) {
                int idx = tid + 256 * q;
                int row = idx >> 2, seg = idx & 3;
                cp16(db + (row >> 6) * MSTR + (row & 63) * PITCH80 + seg * 16,
                     g_GQ + (size_t)row * NROWS + jc + seg * 16);
            }
            cp_commit();
            cp_wait1();
        } else {
            cp_wait0();
        }
        __syncthreads();

        const uint32_t buf = sb + (ch & 1) * BUFB;
        #pragma unroll
        for (int ks = 0; ks < 2; ks++) {
            uint32_t afr[3][2][4];
            #pragma unroll
            for (int m = 0; m < 3; m++)
                #pragma unroll
                for (int mt = 0; mt < 2; mt++)
                    ldm4(afr[m][mt], buf + m * MSTR + (mh * 32 + mt * 16) * PITCH80
                                     + ks * 32 + lmo);
            #pragma unroll
            for (int nt = 0; nt < 4; nt++) {
                #pragma unroll
                for (int m = 0; m < 3; m++) {
                    uint32_t kk = 0x01010101u * (m + 1);
                    uint32_t b0 = __vcmpeq4(pk1[ks][nt], kk) & 0x01010101u;
                    uint32_t b1 = __vcmpeq4(pk2[ks][nt], kk) & 0x01010101u;
                    mma_s8(acc[nt][0], afr[m][0], b0, b1);
                    mma_s8(acc[nt][1], afr[m][1], b0, b1);
                }
            }
        }
        __syncthreads();
    }

    // ---- epilogue: fold hi + lo/127 via smem, write split partial (unscaled) ----
    float* tp = (float*)dyn;          // [128][33] fp32
    if (mh == 0) {
        #pragma unroll
        for (int nt = 0; nt < 4; nt++)
            #pragma unroll
            for (int mt = 0; mt < 2; mt++)
                #pragma unroll
                for (int q = 0; q < 4; q++) {
                    int il = ih * 32 + nt * 8 + t * 2 + (q & 1);
                    int c  = mt * 16 + g + (q >> 1) * 8;
                    tp[il * 33 + c] = (float)acc[nt][mt][q];
                }
    }
    __syncthreads();
    if (mh == 1) {
        #pragma unroll
        for (int nt = 0; nt < 4; nt++)
            #pragma unroll
            for (int mt = 0; mt < 2; mt++)
                #pragma unroll
                for (int q = 0; q < 4; q++) {
                    int il = ih * 32 + nt * 8 + t * 2 + (q & 1);
                    int c  = mt * 16 + g + (q >> 1) * 8;
                    tp[il * 33 + c] += (float)acc[nt][mt][q] * (1.0f / 127.0f);
                }
    }
    __syncthreads();
    #pragma unroll
    for (int q = 0; q < 16; q++) {
        int idx = tid + 256 * q;
        int r = idx >> 5, c = idx & 31;
        g_PartZ[((size_t)blockIdx.y * NROWS + i0 + r) * 32 + c] = tp[r * 33 + c];
    }
}

// ---------------- combine splits, scale, bias, relu ----------------
__global__ void combine_kernel(const float* __restrict__ bias, int mode, int layer) {
    __shared__ float colacc[32];
    int tid = threadIdx.x;
    if (tid < 32) colacc[tid] = 0.f;
    __syncthreads();

    int gi  = blockIdx.x * 256 + tid;
    int row = gi >> 3;
    int c0  = (gi & 7) * 4;
    float4 s = make_float4(0.f, 0.f, 0.f, 0.f);
    #pragma unroll
    for (int sp = 0; sp < NSPLIT; sp++) {
        float4 p = *(const float4*)(g_PartZ + ((size_t)sp * NROWS + row) * 32 + c0);
        s.x += p.x; s.y += p.y; s.z += p.z; s.w += p.w;
    }
    float f0 = __int_as_float(g_cmaxi[layer][c0 + 0]) * (1.0f / 127.0f);
    float f1 = __int_as_float(g_cmaxi[layer][c0 + 1]) * (1.0f / 127.0f);
    float f2 = __int_as_float(g_cmaxi[layer][c0 + 2]) * (1.0f / 127.0f);
    float f3 = __int_as_float(g_cmaxi[layer][c0 + 3]) * (1.0f / 127.0f);
    s.x = fmaxf(s.x * f0 + __ldg(bias + c0 + 0), 0.f);
    s.y = fmaxf(s.y * f1 + __ldg(bias + c0 + 1), 0.f);
    s.z = fmaxf(s.z * f2 + __ldg(bias + c0 + 2), 0.f);
    s.w = fmaxf(s.w * f3 + __ldg(bias + c0 + 3), 0.f);

    if (mode == 0) {
        *(float4*)(g_Z + (size_t)row * 32 + c0) = s;
    } else {
        atomicAdd(&colacc[c0 + 0], s.x);
        atomicAdd(&colacc[c0 + 1], s.y);
        atomicAdd(&colacc[c0 + 2], s.z);
        atomicAdd(&colacc[c0 + 3], s.w);
        __syncthreads();
        if (tid < 32) atomicAdd(&g_colsum[tid * 32], colacc[tid]);
    }
}

// ---------------- FC head ----------------
__global__ void fc_kernel(const float* __restrict__ W0, const float* __restrict__ b0,
                          const float* __restrict__ W1, const float* __restrict__ b1,
                          float* __restrict__ out) {
    int lane = threadIdx.x;
    __shared__ float s[32];
    s[lane] = g_colsum[lane * 32];
    __syncwarp();
    float acc = __ldg(b0 + lane);
    #pragma unroll
    for (int i = 0; i < 32; i++) acc = fmaf(s[i], __ldg(W0 + lane * 32 + i), acc);
    float y = fmaxf(acc, 0.f);
    float p = y * __ldg(W1 + lane);
    #pragma unroll
    for (int o = 16; o; o >>= 1) p += __shfl_xor_sync(0xffffffffu, p, o);
    if (lane == 0) out[0] = 1.0f / (1.0f + expf(-(p + __ldg(b1))));
}

// ---------------- launch ----------------
extern "C" void kernel_launch(void* const* d_in, const int* in_sizes, int n_in,
                              void* d_out, int out_size) {
    (void)in_sizes; (void)n_in; (void)out_size;
    const float* V    = (const float*)d_in[0];
    const int*   adj  = (const int*)  d_in[1];
    const float* w1_0 = (const float*)d_in[2];
    const float* w2_0 = (const float*)d_in[3];
    const float* w3_0 = (const float*)d_in[4];
    const float* gb_0 = (const float*)d_in[5];
    const float* w1_1 = (const float*)d_in[6];
    const float* w2_1 = (const float*)d_in[7];
    const float* w3_1 = (const float*)d_in[8];
    const float* gb_1 = (const float*)d_in[9];
    const float* fcW0 = (const float*)d_in[10];
    const float* fcb0 = (const float*)d_in[11];
    const float* fcW1 = (const float*)d_in[12];
    const float* fcb1 = (const float*)d_in[13];

    dim3 ag(NROWS / 128, NSPLIT);   // 64 x 4 = 256 CTAs

    init_kernel<<<4, 256>>>();
    gt_kernel<<<256, 256>>>(V, 0, w1_0, w2_0, w3_0, 0);
    quant_kernel<<<768, 256>>>(0);
    agg_kernel<1><<<ag, 256, SMEM_DYN>>>(adj);
    combine_kernel<<<256, 256>>>(gb_0, 0, 0);
    gt_kernel<<<256, 256>>>(nullptr, 1, w1_1, w2_1, w3_1, 1);
    quant_kernel<<<768, 256>>>(1);
    agg_kernel<0><<<ag, 256, SMEM_DYN>>>(adj);
    combine_kernel<<<256, 256>>>(gb_1, 1, 1);
    fc_kernel<<<1, 32>>>(fcW0, fcb0, fcW1, fcb1, (float*)d_out);
}